// round 2
// baseline (speedup 1.0000x reference)
#include <cuda_runtime.h>

// HoG layer, fused, occupancy-optimized:
//   input  x: (1, 3, 4096, 4096) f32
//   output feat: (511, 511, 36) f32
// Phase 1: per-cell 9-bin histograms (tile + halo) into SMEM.
// Phase 2: 2x2-cell block normalize; TWO-PASS over SMEM so no blk[36]
//          register array exists -> regs <= 32 -> 8 CTAs/SM.

#define IMG   4096
#define CELLS 512
#define OUTD  511
#define TC    16          // cells per tile side
#define HW    (TC + 1)    // 17: tile + halo
#define NCELL (HW * HW)   // 289

__global__ __launch_bounds__(256, 8)
void hog_fused_kernel(const float* __restrict__ x, float* __restrict__ out)
{
    __shared__ float hist[NCELL * 9];   // 2601 floats = 10404 B

    const int cx0 = blockIdx.x * TC;
    const int cy0 = blockIdx.y * TC;
    const int tid = threadIdx.x;
    const long chs = (long)IMG * IMG;   // channel stride

    // ---- Phase 1: per-cell histogram into SMEM (tile + halo) ----
    for (int c = tid; c < NCELL; c += 256) {
        const int lcy = c / HW;
        const int lcx = c - lcy * HW;
        const int cy = cy0 + lcy;
        const int cx = cx0 + lcx;

        float* hrow = &hist[c * 9];
        #pragma unroll
        for (int b = 0; b < 9; b++) hrow[b] = 0.0f;

        if (cy < CELLS && cx < CELLS) {
            const int py = cy * 8 + 7;
            const int px = cx * 8 + 7;
            const float* p = x + (long)py * IMG + px;

            const bool has_d = (py + 1 < IMG);   // false only for cy == 511
            const bool has_r = (px + 1 < IMG);   // false only for cx == 511

            // Issue all 12 loads up front for max MLP; single-use -> evict-first.
            float u0 = __ldcs(p - IMG);
            float u1 = __ldcs(p - IMG + chs);
            float u2 = __ldcs(p - IMG + 2 * chs);
            float l0 = __ldcs(p - 1);
            float l1 = __ldcs(p - 1 + chs);
            float l2 = __ldcs(p - 1 + 2 * chs);
            float d0 = 0.f, d1 = 0.f, d2 = 0.f;
            float r0 = 0.f, r1 = 0.f, r2 = 0.f;
            if (has_d) {
                d0 = __ldcs(p + IMG);
                d1 = __ldcs(p + IMG + chs);
                d2 = __ldcs(p + IMG + 2 * chs);
            }
            if (has_r) {
                r0 = __ldcs(p + 1);
                r1 = __ldcs(p + 1 + chs);
                r2 = __ldcs(p + 1 + 2 * chs);
            }

            const float gv = (d0 + d1 + d2) - (u0 + u1 + u2);
            const float gh = (r0 + r1 + r2) - (l0 + l1 + l2);
            const float mag = sqrtf(gv * gv + gh * gh + 1e-6f);
            const float ang = fabsf(atanf(gh / (gv + 1e-9f)))
                              * (180.0f / 3.14159265358979323846f);

            // j = floor(ang/20 - 0.5), ang in [0, 90] -> j in [-1, 4]
            const float t  = ang * 0.05f;                // ang / DELTA
            const int   ji = (int)floorf(t - 0.5f);
            const float vj  = mag * ((float)ji + 1.5f - t);
            const float vj1 = mag - vj;

            const int i0 = (ji < 0) ? 8 : ji;   // mod(ji, 9)
            const int i1 = ji + 1;              // in [0, 5], never == i0
            hrow[i0] = vj;
            hrow[i1] = vj1;
        }
    }
    __syncthreads();

    // ---- Phase 2: one output block per thread, two passes over SMEM ----
    const int ly = tid >> 4;          // tid / 16
    const int lx = tid & 15;          // tid % 16
    const int oy = cy0 + ly;
    const int ox = cx0 + lx;
    if (oy >= OUTD || ox >= OUTD) return;

    const float* hb = &hist[(ly * HW + lx) * 9];
    // segment bases: h00, h01, h10, h11
    const int seg_off[4] = {0, 9, HW * 9, HW * 9 + 9};

    // Pass A: sum of squares (no big register array)
    float ss = 0.f;
    #pragma unroll
    for (int s = 0; s < 4; s++) {
        const float* h = hb + seg_off[s];
        #pragma unroll
        for (int b = 0; b < 9; b++) {
            const float v = h[b];
            ss += v * v;
        }
    }
    const float inv = 1.0f / (sqrtf(ss) + 1e-9f);

    // Pass B: re-read, scale, store as 9x float4 (36 floats, 16B aligned)
    float4* o4 = reinterpret_cast<float4*>(out + ((size_t)oy * OUTD + ox) * 36);
    #pragma unroll
    for (int g = 0; g < 9; g++) {
        // flat indices 4g..4g+3 ; segment = i/9, offset = i%9 (constants after unroll)
        float v[4];
        #pragma unroll
        for (int k = 0; k < 4; k++) {
            const int i = 4 * g + k;
            v[k] = hb[seg_off[i / 9] + (i % 9)] * inv;
        }
        o4[g] = make_float4(v[0], v[1], v[2], v[3]);
    }
}

extern "C" void kernel_launch(void* const* d_in, const int* in_sizes, int n_in,
                              void* d_out, int out_size)
{
    const float* x = (const float*)d_in[0];
    float* out = (float*)d_out;
    dim3 grid(CELLS / TC, CELLS / TC);   // 32 x 32 tiles
    hog_fused_kernel<<<grid, 256>>>(x, out);
}

// round 3
// speedup vs baseline: 1.3352x; 1.3352x over previous
#include <cuda_runtime.h>

// HoG layer, fused. R1 structure (proven 24.9us) + explicit 2-cell batching
// in phase 1 so all 24 gather loads issue before any compute (2x MLP/thread).
//   input  x: (1, 3, 4096, 4096) f32
//   output feat: (511, 511, 36) f32

#define IMG   4096
#define CELLS 512
#define OUTD  511
#define TC    16          // cells per tile side
#define HW    (TC + 1)    // 17: tile + halo
#define NCELL (HW * HW)   // 289

__global__ __launch_bounds__(256)
void hog_fused_kernel(const float* __restrict__ x, float* __restrict__ out)
{
    __shared__ float hist[NCELL * 9];   // 2601 floats = 10404 B

    const int cx0 = blockIdx.x * TC;
    const int cy0 = blockIdx.y * TC;
    const int tid = threadIdx.x;
    const long chs = (long)IMG * IMG;   // channel stride

    // Zero all hist slots this thread owns (same cells it fills below,
    // so no barrier needed before the fill).
    for (int c = tid; c < NCELL; c += 256) {
        #pragma unroll
        for (int b = 0; b < 9; b++) hist[c * 9 + b] = 0.0f;
    }

    // ---- Phase 1: two cells per thread, all loads issued up front ----
    float v[2][12];
    bool  valid[2];
    const float* base[2];
    bool  hd[2], hr[2];
    int   cellc[2];

    #pragma unroll
    for (int it = 0; it < 2; it++) {
        const int c = tid + it * 256;
        cellc[it] = c;
        const int lcy = c / HW;
        const int lcx = c - lcy * HW;
        const int cy = cy0 + lcy;
        const int cx = cx0 + lcx;
        valid[it] = (c < NCELL) && (cy < CELLS) && (cx < CELLS);
        const int py = cy * 8 + 7;
        const int px = cx * 8 + 7;
        base[it] = x + (long)py * IMG + px;
        hd[it] = (py + 1 < IMG);
        hr[it] = (px + 1 < IMG);
    }

    // Batched, predicated gather: 24 LDGs in flight.
    #pragma unroll
    for (int it = 0; it < 2; it++) {
        const float* p = base[it];
        const bool va = valid[it];
        const bool vd = va && hd[it];
        const bool vr = va && hr[it];
        #pragma unroll
        for (int ch = 0; ch < 3; ch++) {
            const float* pc = p + ch * chs;
            v[it][ch * 4 + 0] = va ? pc[-IMG] : 0.0f;
            v[it][ch * 4 + 1] = va ? pc[-1]   : 0.0f;
            v[it][ch * 4 + 2] = vd ? pc[IMG]  : 0.0f;
            v[it][ch * 4 + 3] = vr ? pc[1]    : 0.0f;
        }
    }

    #pragma unroll
    for (int it = 0; it < 2; it++) {
        if (!valid[it]) continue;
        const float su = v[it][0] + v[it][4] + v[it][8];
        const float sl = v[it][1] + v[it][5] + v[it][9];
        const float sd = v[it][2] + v[it][6] + v[it][10];
        const float sr = v[it][3] + v[it][7] + v[it][11];

        const float gv = sd - su;
        const float gh = sr - sl;
        const float mag = sqrtf(gv * gv + gh * gh + 1e-6f);
        const float ang = fabsf(atanf(gh / (gv + 1e-9f)))
                          * (180.0f / 3.14159265358979323846f);

        // j = floor(ang/20 - 0.5), ang in [0, 90] -> j in [-1, 4]
        const float t  = ang * 0.05f;
        const int   ji = (int)floorf(t - 0.5f);
        const float vj  = mag * ((float)ji + 1.5f - t);
        const float vj1 = mag - vj;

        const int i0 = (ji < 0) ? 8 : ji;   // mod(ji, 9)
        const int i1 = ji + 1;              // in [0, 5], never == i0
        float* hrow = &hist[cellc[it] * 9];
        hrow[i0] = vj;
        hrow[i1] = vj1;
    }
    __syncthreads();

    // ---- Phase 2: one output block per thread (R1 version) ----
    const int ly = tid >> 4;
    const int lx = tid & 15;
    const int oy = cy0 + ly;
    const int ox = cx0 + lx;
    if (oy >= OUTD || ox >= OUTD) return;

    const float* h00 = &hist[(ly * HW + lx) * 9];
    const float* h01 = h00 + 9;
    const float* h10 = h00 + HW * 9;
    const float* h11 = h10 + 9;

    float blk[36];
    #pragma unroll
    for (int b = 0; b < 9; b++) {
        blk[b]      = h00[b];
        blk[9  + b] = h01[b];
        blk[18 + b] = h10[b];
        blk[27 + b] = h11[b];
    }

    float ss = 0.f;
    #pragma unroll
    for (int b = 0; b < 36; b++) ss += blk[b] * blk[b];
    const float inv = 1.0f / (sqrtf(ss) + 1e-9f);

    float4* o4 = reinterpret_cast<float4*>(out + ((size_t)oy * OUTD + ox) * 36);
    #pragma unroll
    for (int b = 0; b < 9; b++) {
        o4[b] = make_float4(blk[4 * b + 0] * inv,
                            blk[4 * b + 1] * inv,
                            blk[4 * b + 2] * inv,
                            blk[4 * b + 3] * inv);
    }
}

extern "C" void kernel_launch(void* const* d_in, const int* in_sizes, int n_in,
                              void* d_out, int out_size)
{
    const float* x = (const float*)d_in[0];
    float* out = (float*)d_out;
    dim3 grid(CELLS / TC, CELLS / TC);   // 32 x 32 tiles
    hog_fused_kernel<<<grid, 256>>>(x, out);
}